// round 13
// baseline (speedup 1.0000x reference)
#include <cuda_runtime.h>

// RoIPooling2D (Caffe roi_pool, max) — NHWC gather, fine-grained blocks.
// x [B=2,C=256,H=50,W=50] f32, rois [N,5], out [N,256,7,7] f32.
// Bounds replicate XLA:GPU arithmetic exactly (div.full.f32, proven Round 3).
//
//   1) transpose_in: NCHW -> g_xt NHWC; block (0,0,0) also fills per-ROI
//      bounds tables (g_bidx/g_hs/g_he/g_ws/g_we) — no extra launch.
//   2) gather: grid (N, 2 ch-halves, 7 bin-rows) = 1792 blocks, 512 thr.
//      warp = (pw, 64-ch sub): ONE bounds read, ONE 16-load clamped
//      exposure (regs=55 proven in flight), ONE fold, ONE STS. Then a tiny
//      coalesced write of 896 staged floats.

#define POOL_H 7
#define POOL_W 7
#define NBINS  (POOL_H * POOL_W)       // 49
#define SPATIAL_SCALE 0.0625f
#define C_TOT  256
#define HDIM   50
#define WDIM   50
#define HW     (HDIM * WDIM)
#define CH     128                     // channels per gather block (half)
#define MAX_N  512
#define GTHREADS 512
#define NEG_FLT_MAX (-3.402823466e38f)

__device__ float g_xt[2 * HW * C_TOT];  // NHWC scratch, 5.12 MB
__device__ int g_bidx[MAX_N];
__device__ int g_hs[MAX_N * POOL_H];
__device__ int g_he[MAX_N * POOL_H];
__device__ int g_ws[MAX_N * POOL_W];
__device__ int g_we[MAX_N * POOL_W];

__device__ __forceinline__ float div_full(float a, float b) {
    float r;
    asm("div.full.f32 %0, %1, %2;" : "=f"(r) : "f"(a), "f"(b));
    return r;
}

__device__ __forceinline__ float2 ld2(const float* p) {
    return __ldg(reinterpret_cast<const float2*>(p));
}
__device__ __forceinline__ void mx(float2& m, float2 v) {
    m.x = fmaxf(m.x, v.x);
    m.y = fmaxf(m.y, v.y);
}

// ---------------- Kernel 1: transpose + fused bounds table ----------------
__global__ void transpose_in_kernel(const float* __restrict__ x,
                                    const float* __restrict__ rois, int N) {
    __shared__ float tile[32][33];
    int b  = blockIdx.z;
    int p0 = blockIdx.x * 32;
    int c0 = blockIdx.y * 32;
    int tx = threadIdx.x;
    int ty = threadIdx.y;
    int tid = ty * 32 + tx;

    // Block (0,0,0): also compute per-ROI bounds (exact reference arithmetic).
    if (blockIdx.x == 0 && blockIdx.y == 0 && blockIdx.z == 0) {
        for (int n = tid; n < N; n += 256) {
            const float* r = rois + n * 5;
            g_bidx[n] = (int)r[0];
            float sx = rintf(__fmul_rn(r[1], SPATIAL_SCALE));
            float sy = rintf(__fmul_rn(r[2], SPATIAL_SCALE));
            float ex = rintf(__fmul_rn(r[3], SPATIAL_SCALE));
            float ey = rintf(__fmul_rn(r[4], SPATIAL_SCALE));
            float roi_w = fmaxf(__fadd_rn(__fsub_rn(ex, sx), 1.0f), 1.0f);
            float roi_h = fmaxf(__fadd_rn(__fsub_rn(ey, sy), 1.0f), 1.0f);
            float bw = div_full(roi_w, (float)POOL_W);
            float bh = div_full(roi_h, (float)POOL_H);
            #pragma unroll
            for (int i = 0; i < POOL_H; ++i) {
                float lo = __fadd_rn(floorf(__fmul_rn((float)i, bh)), sy);
                float hi = __fadd_rn(ceilf(__fmul_rn((float)(i + 1), bh)), sy);
                g_hs[n * POOL_H + i] = (int)fminf(fmaxf(lo, 0.0f), (float)HDIM);
                g_he[n * POOL_H + i] = (int)fminf(fmaxf(hi, 0.0f), (float)HDIM);
            }
            #pragma unroll
            for (int j = 0; j < POOL_W; ++j) {
                float lo = __fadd_rn(floorf(__fmul_rn((float)j, bw)), sx);
                float hi = __fadd_rn(ceilf(__fmul_rn((float)(j + 1), bw)), sx);
                g_ws[n * POOL_W + j] = (int)fminf(fmaxf(lo, 0.0f), (float)WDIM);
                g_we[n * POOL_W + j] = (int)fminf(fmaxf(hi, 0.0f), (float)WDIM);
            }
        }
    }

    #pragma unroll
    for (int k = 0; k < 4; ++k) {
        int c = c0 + ty + k * 8;
        int p = p0 + tx;
        if (p < HW)
            tile[ty + k * 8][tx] = x[((size_t)b * C_TOT + c) * HW + p];
    }
    __syncthreads();
    #pragma unroll
    for (int k = 0; k < 4; ++k) {
        int p = p0 + ty + k * 8;
        int c = c0 + tx;
        if (p < HW)
            g_xt[((size_t)b * HW + p) * C_TOT + c] = tile[tx][ty + k * 8];
    }
}

// ---------------- Kernel 2: one-exposure-per-warp gather ----------------
__global__ void __launch_bounds__(GTHREADS, 2)
roi_gather_kernel(float* __restrict__ out, int N) {
    __shared__ float s_res[CH * POOL_W];   // [c_local][pw], 896 floats

    int n    = blockIdx.x;
    int half = blockIdx.y;                 // 128-channel half
    int ph   = blockIdx.z;                 // bin row
    int tid  = threadIdx.x;
    int warp = tid >> 5;
    int lane = tid & 31;

    if (warp < 14) {
        int pw  = warp >> 1;               // 0..6
        int sub = warp & 1;                // 64-ch sub-half

        int b  = g_bidx[n];
        int hs = g_hs[n * POOL_H + ph];
        int he = g_he[n * POOL_H + ph];
        int ws = g_ws[n * POOL_W + pw];
        int we = g_we[n * POOL_W + pw];
        int wh = he - hs, ww = we - ws;

        const float* xroi = g_xt + (size_t)b * (HW * C_TOT) + half * CH
                                 + sub * 64 + lane * 2;

        float2 m;
        if (wh > 0 && ww > 0 && wh <= 4 && ww <= 4) {
            const float* base = xroi + ((size_t)(hs * WDIM) + ws) * C_TOT;
            // Clamped offsets: duplicates harmless under max.
            int h1 = min(1, wh - 1) * (WDIM * C_TOT);
            int h2 = min(2, wh - 1) * (WDIM * C_TOT);
            int h3 = min(3, wh - 1) * (WDIM * C_TOT);
            int w1 = min(1, ww - 1) * C_TOT;
            int w2 = min(2, ww - 1) * C_TOT;
            int w3 = min(3, ww - 1) * C_TOT;

            float2 a00 = ld2(base);
            float2 a01 = ld2(base + w1);
            float2 a02 = ld2(base + w2);
            float2 a03 = ld2(base + w3);
            float2 a10 = ld2(base + h1);
            float2 a11 = ld2(base + h1 + w1);
            float2 a12 = ld2(base + h1 + w2);
            float2 a13 = ld2(base + h1 + w3);
            float2 a20 = ld2(base + h2);
            float2 a21 = ld2(base + h2 + w1);
            float2 a22 = ld2(base + h2 + w2);
            float2 a23 = ld2(base + h2 + w3);
            float2 a30 = ld2(base + h3);
            float2 a31 = ld2(base + h3 + w1);
            float2 a32 = ld2(base + h3 + w2);
            float2 a33 = ld2(base + h3 + w3);

            mx(a00, a01); mx(a02, a03);
            mx(a10, a11); mx(a12, a13);
            mx(a20, a21); mx(a22, a23);
            mx(a30, a31); mx(a32, a33);
            mx(a00, a02); mx(a10, a12); mx(a20, a22); mx(a30, a32);
            mx(a00, a10); mx(a20, a30);
            mx(a00, a20);
            m = a00;
        } else if (wh > 0 && ww > 0) {
            // Fallback (never hit with this data shape, kept for safety).
            m = make_float2(NEG_FLT_MAX, NEG_FLT_MAX);
            const float* rowp = xroi + ((size_t)(hs * WDIM) + ws) * C_TOT;
            for (int h = 0; h < wh; ++h) {
                const float* q = rowp;
                for (int w = 0; w < ww; ++w) { mx(m, ld2(q)); q += C_TOT; }
                rowp += WDIM * C_TOT;
            }
        } else {
            m = make_float2(0.f, 0.f);
        }

        int c = sub * 64 + lane * 2;
        s_res[(c + 0) * POOL_W + pw] = m.x;
        s_res[(c + 1) * POOL_W + pw] = m.y;
    }
    __syncthreads();

    // Write: out[n][half*128 + c][ph*7 + pw]; 7-float contiguous run per ch.
    float* obase = out + (size_t)n * (C_TOT * NBINS)
                       + (size_t)half * (CH * NBINS) + ph * POOL_W;
    #pragma unroll
    for (int k = 0; k < 2; ++k) {
        int i = tid + k * GTHREADS;
        if (i < CH * POOL_W) {
            int c = i / POOL_W;            // const divisor -> mulhi
            int j = i - c * POOL_W;
            obase[c * NBINS + j] = s_res[i];
        }
    }
}

extern "C" void kernel_launch(void* const* d_in, const int* in_sizes, int n_in,
                              void* d_out, int out_size) {
    const float* x    = (const float*)d_in[0];   // [B,256,50,50]
    const float* rois = (const float*)d_in[1];   // [N,5]
    float* out = (float*)d_out;                  // [N,256,7,7]

    const int N = in_sizes[1] / 5;
    const int B = in_sizes[0] / (C_TOT * HW);

    dim3 tgrid((HW + 31) / 32, C_TOT / 32, B);
    dim3 tblock(32, 8);
    transpose_in_kernel<<<tgrid, tblock>>>(x, rois, N);

    dim3 ggrid(N, C_TOT / CH, POOL_H);           // (128, 2, 7) = 1792 blocks
    roi_gather_kernel<<<ggrid, GTHREADS>>>(out, N);
}

// round 14
// speedup vs baseline: 1.3175x; 1.3175x over previous
#include <cuda_runtime.h>

// RoIPooling2D (Caffe roi_pool, max) — NHWC gather, exact-rows batched loads.
// x [B=2,C=256,H=50,W=50] f32, rois [N,5], out [N,256,7,7] f32.
// Bounds replicate XLA:GPU arithmetic exactly (div.full.f32, proven Round 3).
//
// R12 structure (grid (N,2), 512thr, lb(512,2), smem staging) with the unit
// gather branched on warp-uniform wh in {1..4}: each path is a straight-line
// batch of wh x 4 clamped-width float2 loads -> ONE latency exposure per unit
// at ~exact byte traffic (row clamping eliminated; width clamp dups hit L1).

#define POOL_H 7
#define POOL_W 7
#define NBINS  (POOL_H * POOL_W)       // 49
#define SPATIAL_SCALE 0.0625f
#define C_TOT  256
#define HDIM   50
#define WDIM   50
#define HW     (HDIM * WDIM)
#define CH     128                     // channels per gather block (half)
#define NUNITS (NBINS * 2)             // 98: (bin, 64-ch sub-half)
#define GTHREADS 512
#define NWARPS (GTHREADS / 32)
#define NEG_FLT_MAX (-3.402823466e38f)

__device__ float g_xt[2 * HW * C_TOT];  // NHWC scratch, 5.12 MB

__device__ __forceinline__ float div_full(float a, float b) {
    float r;
    asm("div.full.f32 %0, %1, %2;" : "=f"(r) : "f"(a), "f"(b));
    return r;
}

__device__ __forceinline__ float2 ld2(const float* p) {
    return __ldg(reinterpret_cast<const float2*>(p));
}
__device__ __forceinline__ void mx(float2& m, float2 v) {
    m.x = fmaxf(m.x, v.x);
    m.y = fmaxf(m.y, v.y);
}

// Straight-line gather of WH rows x 4 clamped-width float2 loads.
// All loads unconditional & independent -> one latency exposure.
template <int WH>
__device__ __forceinline__ float2 gather_unit(const float* base,
                                              int w1, int w2, int w3) {
    float2 r[WH][4];
    #pragma unroll
    for (int h = 0; h < WH; ++h) {
        const float* rp = base + h * (WDIM * C_TOT);
        r[h][0] = ld2(rp);
        r[h][1] = ld2(rp + w1);
        r[h][2] = ld2(rp + w2);
        r[h][3] = ld2(rp + w3);
    }
    #pragma unroll
    for (int h = 0; h < WH; ++h) {
        mx(r[h][0], r[h][1]);
        mx(r[h][2], r[h][3]);
        mx(r[h][0], r[h][2]);
    }
    #pragma unroll
    for (int h = 1; h < WH; ++h)
        mx(r[0][0], r[h][0]);
    return r[0][0];
}

// ---------------- Kernel 1: NCHW -> NHWC transpose (proven, ~2.4us) ----------------
__global__ void transpose_in_kernel(const float* __restrict__ x) {
    __shared__ float tile[32][33];
    int b  = blockIdx.z;
    int p0 = blockIdx.x * 32;
    int c0 = blockIdx.y * 32;
    int tx = threadIdx.x;
    int ty = threadIdx.y;

    #pragma unroll
    for (int k = 0; k < 4; ++k) {
        int c = c0 + ty + k * 8;
        int p = p0 + tx;
        if (p < HW)
            tile[ty + k * 8][tx] = x[((size_t)b * C_TOT + c) * HW + p];
    }
    __syncthreads();
    #pragma unroll
    for (int k = 0; k < 4; ++k) {
        int p = p0 + ty + k * 8;
        int c = c0 + tx;
        if (p < HW)
            g_xt[((size_t)b * HW + p) * C_TOT + c] = tile[tx][ty + k * 8];
    }
}

// ---------------- Kernel 2: fused bounds + exact-row batched gather ----------------
__global__ void __launch_bounds__(GTHREADS, 2)
roi_gather_kernel(const float* __restrict__ rois, float* __restrict__ out, int N) {
    __shared__ float s_res[CH * NBINS];   // flat [c][bin], 25 KB
    __shared__ int   s_hs[POOL_H], s_he[POOL_H], s_ws[POOL_W], s_we[POOL_W];
    __shared__ int   s_b;

    int n    = blockIdx.x;
    int half = blockIdx.y;                 // 128-channel half
    int tid  = threadIdx.x;
    int warp = tid >> 5;
    int lane = tid & 31;

    // --- bounds (exact replica of reference arithmetic, incl. div.full) ---
    if (tid < POOL_H + POOL_W + 1) {
        const float* r = rois + n * 5;
        if (tid == POOL_H + POOL_W) {
            s_b = (int)r[0];
        } else {
            bool is_h = (tid < POOL_H);
            int  i    = is_h ? tid : tid - POOL_H;
            float s1  = rintf(__fmul_rn(r[is_h ? 2 : 1], SPATIAL_SCALE));
            float e1  = rintf(__fmul_rn(r[is_h ? 4 : 3], SPATIAL_SCALE));
            float sz  = fmaxf(__fadd_rn(__fsub_rn(e1, s1), 1.0f), 1.0f);
            float bs  = div_full(sz, is_h ? (float)POOL_H : (float)POOL_W);
            float npx = is_h ? (float)HDIM : (float)WDIM;
            float lo = __fadd_rn(floorf(__fmul_rn((float)i, bs)), s1);
            float hi = __fadd_rn(ceilf(__fmul_rn((float)(i + 1), bs)), s1);
            lo = fminf(fmaxf(lo, 0.0f), npx);
            hi = fminf(fmaxf(hi, 0.0f), npx);
            if (is_h) { s_hs[i] = (int)lo; s_he[i] = (int)hi; }
            else      { s_ws[i] = (int)lo; s_we[i] = (int)hi; }
        }
    }
    __syncthreads();

    // --- gather: unit = (bin, 64-ch sub-half); lane = 2 channels (float2) ---
    const float* xroi = g_xt + (size_t)s_b * (HW * C_TOT) + half * CH;

    for (int u = warp; u < NUNITS; u += NWARPS) {
        int bin = u >> 1;
        int sub = u & 1;
        int ph  = bin / POOL_W;
        int pw  = bin - ph * POOL_W;
        int hs = s_hs[ph], he = s_he[ph];
        int ws = s_ws[pw], we = s_we[pw];
        int wh = he - hs, ww = we - ws;

        float2 m;
        if (wh > 0 && ww > 0 && wh <= 4 && ww <= 4) {
            const float* base = xroi + ((size_t)(hs * WDIM) + ws) * C_TOT
                                     + sub * 64 + lane * 2;
            // Width offsets clamped (duplicates hit the just-fetched L1 line).
            int w1 = min(1, ww - 1) * C_TOT;
            int w2 = min(2, ww - 1) * C_TOT;
            int w3 = min(3, ww - 1) * C_TOT;
            // Warp-uniform branch on exact row count -> straight-line batch.
            switch (wh) {
                case 1: m = gather_unit<1>(base, w1, w2, w3); break;
                case 2: m = gather_unit<2>(base, w1, w2, w3); break;
                case 3: m = gather_unit<3>(base, w1, w2, w3); break;
                default: m = gather_unit<4>(base, w1, w2, w3); break;
            }
        } else if (wh > 0 && ww > 0) {
            // Fallback (never hit with this data shape, kept for safety).
            m = make_float2(NEG_FLT_MAX, NEG_FLT_MAX);
            const float* rowp = xroi + ((size_t)(hs * WDIM) + ws) * C_TOT
                                     + sub * 64 + lane * 2;
            for (int h = 0; h < wh; ++h) {
                const float* q = rowp;
                for (int w = 0; w < ww; ++w) { mx(m, ld2(q)); q += C_TOT; }
                rowp += WDIM * C_TOT;
            }
        } else {
            m = make_float2(0.f, 0.f);
        }

        int c = sub * 64 + lane * 2;                 // local channel
        s_res[(c + 0) * NBINS + bin] = m.x;
        s_res[(c + 1) * NBINS + bin] = m.y;
    }
    __syncthreads();

    // --- coalesced staged write: flat 6272 floats = 1568 float4 ---
    float* obase = out + (size_t)n * (C_TOT * NBINS) + (size_t)half * (CH * NBINS);
    const float4* src = reinterpret_cast<const float4*>(s_res);
    float4* dst = reinterpret_cast<float4*>(obase);
    #pragma unroll
    for (int k = 0; k < (CH * NBINS) / 4 / GTHREADS + 1; ++k) {
        int i = tid + k * GTHREADS;
        if (i < (CH * NBINS) / 4)
            dst[i] = src[i];
    }
}

extern "C" void kernel_launch(void* const* d_in, const int* in_sizes, int n_in,
                              void* d_out, int out_size) {
    const float* x    = (const float*)d_in[0];   // [B,256,50,50]
    const float* rois = (const float*)d_in[1];   // [N,5]
    float* out = (float*)d_out;                  // [N,256,7,7]

    const int N = in_sizes[1] / 5;
    const int B = in_sizes[0] / (C_TOT * HW);

    dim3 tgrid((HW + 31) / 32, C_TOT / 32, B);
    dim3 tblock(32, 8);
    transpose_in_kernel<<<tgrid, tblock>>>(x);

    dim3 ggrid(N, C_TOT / CH);                   // (128, 2) = 256 blocks
    roi_gather_kernel<<<ggrid, GTHREADS>>>(rois, out, N);
}

// round 15
// speedup vs baseline: 1.3208x; 1.0025x over previous
#include <cuda_runtime.h>

// RoIPooling2D (Caffe roi_pool, max) — NHWC gather, exact-window batched loads.
// x [B=2,C=256,H=50,W=50] f32, rois [N,5], out [N,256,7,7] f32.
// Bounds replicate XLA:GPU arithmetic exactly (div.full.f32, proven Round 3).
//
// R14 structure, but the unit gather dispatches on the warp-uniform (wh, ww)
// pair: 16 straight-line paths, each exactly wh*ww unconditional float2 loads
// -> one latency exposure at MINIMAL L2 traffic (~34 MB vs 57 MB clamped).

#define POOL_H 7
#define POOL_W 7
#define NBINS  (POOL_H * POOL_W)       // 49
#define SPATIAL_SCALE 0.0625f
#define C_TOT  256
#define HDIM   50
#define WDIM   50
#define HW     (HDIM * WDIM)
#define CH     128                     // channels per gather block (half)
#define NUNITS (NBINS * 2)             // 98: (bin, 64-ch sub-half)
#define GTHREADS 512
#define NWARPS (GTHREADS / 32)
#define ROWSTRIDE (WDIM * C_TOT)
#define NEG_FLT_MAX (-3.402823466e38f)

__device__ float g_xt[2 * HW * C_TOT];  // NHWC scratch, 5.12 MB

__device__ __forceinline__ float div_full(float a, float b) {
    float r;
    asm("div.full.f32 %0, %1, %2;" : "=f"(r) : "f"(a), "f"(b));
    return r;
}

__device__ __forceinline__ float2 ld2(const float* p) {
    return __ldg(reinterpret_cast<const float2*>(p));
}
__device__ __forceinline__ void mx(float2& m, float2 v) {
    m.x = fmaxf(m.x, v.x);
    m.y = fmaxf(m.y, v.y);
}

// Straight-line gather of exactly WH x WW float2 loads (one exposure).
template <int WH, int WW>
__device__ __forceinline__ float2 gather_unit(const float* base) {
    float2 r[WH][WW];
    #pragma unroll
    for (int h = 0; h < WH; ++h) {
        const float* rp = base + h * ROWSTRIDE;
        #pragma unroll
        for (int w = 0; w < WW; ++w)
            r[h][w] = ld2(rp + w * C_TOT);
    }
    // Fold within rows, then across rows (short dependence chains).
    #pragma unroll
    for (int h = 0; h < WH; ++h) {
        #pragma unroll
        for (int w = 1; w < WW; ++w)
            mx(r[h][0], r[h][w]);
    }
    #pragma unroll
    for (int h = 1; h < WH; ++h)
        mx(r[0][0], r[h][0]);
    return r[0][0];
}

// ---------------- Kernel 1: NCHW -> NHWC transpose (proven, ~2.4us) ----------------
__global__ void transpose_in_kernel(const float* __restrict__ x) {
    __shared__ float tile[32][33];
    int b  = blockIdx.z;
    int p0 = blockIdx.x * 32;
    int c0 = blockIdx.y * 32;
    int tx = threadIdx.x;
    int ty = threadIdx.y;

    #pragma unroll
    for (int k = 0; k < 4; ++k) {
        int c = c0 + ty + k * 8;
        int p = p0 + tx;
        if (p < HW)
            tile[ty + k * 8][tx] = x[((size_t)b * C_TOT + c) * HW + p];
    }
    __syncthreads();
    #pragma unroll
    for (int k = 0; k < 4; ++k) {
        int p = p0 + ty + k * 8;
        int c = c0 + tx;
        if (p < HW)
            g_xt[((size_t)b * HW + p) * C_TOT + c] = tile[tx][ty + k * 8];
    }
}

// ---------------- Kernel 2: fused bounds + exact-window batched gather ----------------
__global__ void __launch_bounds__(GTHREADS, 2)
roi_gather_kernel(const float* __restrict__ rois, float* __restrict__ out, int N) {
    __shared__ float s_res[CH * NBINS];   // flat [c][bin], 25 KB
    __shared__ int   s_hs[POOL_H], s_he[POOL_H], s_ws[POOL_W], s_we[POOL_W];
    __shared__ int   s_b;

    int n    = blockIdx.x;
    int half = blockIdx.y;                 // 128-channel half
    int tid  = threadIdx.x;
    int warp = tid >> 5;
    int lane = tid & 31;

    // --- bounds (exact replica of reference arithmetic, incl. div.full) ---
    if (tid < POOL_H + POOL_W + 1) {
        const float* r = rois + n * 5;
        if (tid == POOL_H + POOL_W) {
            s_b = (int)r[0];
        } else {
            bool is_h = (tid < POOL_H);
            int  i    = is_h ? tid : tid - POOL_H;
            float s1  = rintf(__fmul_rn(r[is_h ? 2 : 1], SPATIAL_SCALE));
            float e1  = rintf(__fmul_rn(r[is_h ? 4 : 3], SPATIAL_SCALE));
            float sz  = fmaxf(__fadd_rn(__fsub_rn(e1, s1), 1.0f), 1.0f);
            float bs  = div_full(sz, is_h ? (float)POOL_H : (float)POOL_W);
            float npx = is_h ? (float)HDIM : (float)WDIM;
            float lo = __fadd_rn(floorf(__fmul_rn((float)i, bs)), s1);
            float hi = __fadd_rn(ceilf(__fmul_rn((float)(i + 1), bs)), s1);
            lo = fminf(fmaxf(lo, 0.0f), npx);
            hi = fminf(fmaxf(hi, 0.0f), npx);
            if (is_h) { s_hs[i] = (int)lo; s_he[i] = (int)hi; }
            else      { s_ws[i] = (int)lo; s_we[i] = (int)hi; }
        }
    }
    __syncthreads();

    // --- gather: unit = (bin, 64-ch sub-half); lane = 2 channels (float2) ---
    const float* xroi = g_xt + (size_t)s_b * (HW * C_TOT) + half * CH;

    for (int u = warp; u < NUNITS; u += NWARPS) {
        int bin = u >> 1;
        int sub = u & 1;
        int ph  = bin / POOL_W;
        int pw  = bin - ph * POOL_W;
        int hs = s_hs[ph], he = s_he[ph];
        int ws = s_ws[pw], we = s_we[pw];
        int wh = he - hs, ww = we - ws;

        float2 m;
        if (wh > 0 && ww > 0 && wh <= 4 && ww <= 4) {
            const float* base = xroi + ((size_t)(hs * WDIM) + ws) * C_TOT
                                     + sub * 64 + lane * 2;
            // Warp-uniform exact-shape dispatch: minimal loads, one exposure.
            switch (((wh - 1) << 2) | (ww - 1)) {
                case  0: m = gather_unit<1,1>(base); break;
                case  1: m = gather_unit<1,2>(base); break;
                case  2: m = gather_unit<1,3>(base); break;
                case  3: m = gather_unit<1,4>(base); break;
                case  4: m = gather_unit<2,1>(base); break;
                case  5: m = gather_unit<2,2>(base); break;
                case  6: m = gather_unit<2,3>(base); break;
                case  7: m = gather_unit<2,4>(base); break;
                case  8: m = gather_unit<3,1>(base); break;
                case  9: m = gather_unit<3,2>(base); break;
                case 10: m = gather_unit<3,3>(base); break;
                case 11: m = gather_unit<3,4>(base); break;
                case 12: m = gather_unit<4,1>(base); break;
                case 13: m = gather_unit<4,2>(base); break;
                case 14: m = gather_unit<4,3>(base); break;
                default: m = gather_unit<4,4>(base); break;
            }
        } else if (wh > 0 && ww > 0) {
            // Fallback (never hit with this data shape, kept for safety).
            m = make_float2(NEG_FLT_MAX, NEG_FLT_MAX);
            const float* rowp = xroi + ((size_t)(hs * WDIM) + ws) * C_TOT
                                     + sub * 64 + lane * 2;
            for (int h = 0; h < wh; ++h) {
                const float* q = rowp;
                for (int w = 0; w < ww; ++w) { mx(m, ld2(q)); q += C_TOT; }
                rowp += ROWSTRIDE;
            }
        } else {
            m = make_float2(0.f, 0.f);
        }

        int c = sub * 64 + lane * 2;                 // local channel
        s_res[(c + 0) * NBINS + bin] = m.x;
        s_res[(c + 1) * NBINS + bin] = m.y;
    }
    __syncthreads();

    // --- coalesced staged write: flat 6272 floats = 1568 float4 ---
    float* obase = out + (size_t)n * (C_TOT * NBINS) + (size_t)half * (CH * NBINS);
    const float4* src = reinterpret_cast<const float4*>(s_res);
    float4* dst = reinterpret_cast<float4*>(obase);
    #pragma unroll
    for (int k = 0; k < (CH * NBINS) / 4 / GTHREADS + 1; ++k) {
        int i = tid + k * GTHREADS;
        if (i < (CH * NBINS) / 4)
            dst[i] = src[i];
    }
}

extern "C" void kernel_launch(void* const* d_in, const int* in_sizes, int n_in,
                              void* d_out, int out_size) {
    const float* x    = (const float*)d_in[0];   // [B,256,50,50]
    const float* rois = (const float*)d_in[1];   // [N,5]
    float* out = (float*)d_out;                  // [N,256,7,7]

    const int N = in_sizes[1] / 5;
    const int B = in_sizes[0] / (C_TOT * HW);

    dim3 tgrid((HW + 31) / 32, C_TOT / 32, B);
    dim3 tblock(32, 8);
    transpose_in_kernel<<<tgrid, tblock>>>(x);

    dim3 ggrid(N, C_TOT / CH);                   // (128, 2) = 256 blocks
    roi_gather_kernel<<<ggrid, GTHREADS>>>(rois, out, N);
}